// round 6
// baseline (speedup 1.0000x reference)
#include <cuda_runtime.h>
#include <cuda_fp16.h>
#include <cmath>
#include <cstdint>

// InstantNGP hash-grid encoder, round 6.
//  * levels 0-2: fp16 vertex grids staged in SMEM (persistent blocks).
//    8 x LDS.32 per query -> off the L1tex pipe entirely.
//  * levels 3-6: cell-packed fp16 tables in global (2 x LDG.128 per query).
//  * levels 7-15: fp16x2 hash tables, 4-entry LDG.128 windows (x-prime==1
//    pair trick); ix%4==3 lanes add 4 x 4B gathers. avg 5 loads.

#define NGP_L 16
#define NGP_T (1u << 19)
#define NGP_MASK ((1u << 19) - 1u)
#define PRIME_Y 2654435761u
#define PRIME_Z 805459861u

#define N_SMEM 3            // levels 0-2 in smem
#define N_CELL 4            // levels 3-6 cell-packed
#define HBASE  (N_SMEM + N_CELL)   // 7
#define NHASH  (NGP_L - HBASE)     // 9

#define QSCALE   65536.0f
#define QSCALE_I (1.0f / 65536.0f)

// vertex grids l0-2: (res+2)^3 = 18^3 + 24^3 + 32^3 = 52,424 half2 entries
#define NV_TOTAL 52424
__device__ unsigned g_vg[NV_TOTAL];

// cell-packed l3-6: sum (r+1)^2*(r+2) = 87,120+208,860+538,002+1,417,472
#define QCAP 2252000
__device__ uint4 g_q[QCAP];

// hashed fp16 tables l7-15
__device__ uint4 g_ht[NHASH * (NGP_T / 4)];

struct NgpParams {
    float cell[NGP_L];
    int   res[NGP_L];
    int   qoff[N_CELL];   // offsets into g_q for levels 3..6
    int   voff[N_SMEM];   // offsets into g_vg for levels 0..2
    int   vD[N_SMEM];     // res+2
};

__device__ __forceinline__ float2 hsel(const uint4& q, unsigned i)
{
    const unsigned v = (i & 2u) ? ((i & 1u) ? q.w : q.z)
                                : ((i & 1u) ? q.y : q.x);
    return __half22float2(*reinterpret_cast<const __half2*>(&v));
}
__device__ __forceinline__ float2 h2f(unsigned v)
{
    return __half22float2(*reinterpret_cast<const __half2*>(&v));
}

// -------- precompute A: vertex grids for levels 0..2 ------------------------
__global__ __launch_bounds__(256)
void ngp_vpack_kernel(const float* __restrict__ tables, NgpParams p)
{
    int id = blockIdx.x * blockDim.x + threadIdx.x;
    if (id >= NV_TOTAL) return;
    int lvl = 0, rel = id;
    #pragma unroll
    for (int l = 0; l < N_SMEM; l++) {
        const int D = p.vD[l];
        const int n = D * D * D;
        if (rel < n) { lvl = l; break; }
        rel -= n;
    }
    const int D = p.vD[lvl];
    const int ix = rel % D;
    const int t  = rel / D;
    const int iy = t % D;
    const int iz = t / D;
    const unsigned h = ((unsigned)ix ^ ((unsigned)iy * PRIME_Y)
                                     ^ ((unsigned)iz * PRIME_Z)) & NGP_MASK;
    const float2 v = __ldg(reinterpret_cast<const float2*>(tables)
                           + (unsigned)lvl * NGP_T + h);
    const __half2 hv = __floats2half2_rn(v.x * QSCALE, v.y * QSCALE);
    g_vg[id] = *reinterpret_cast<const unsigned*>(&hv);
}

// -------- precompute B: cell-packed tables for levels 3..6 ------------------
__global__ __launch_bounds__(256)
void ngp_qpack_kernel(const float* __restrict__ tables, NgpParams p)
{
    const int lvl = N_SMEM + blockIdx.y;          // 3..6
    const int res = p.res[lvl];
    const int D1  = res + 1;
    const int ncell = D1 * D1 * (res + 2);
    const int id = blockIdx.x * blockDim.x + threadIdx.x;
    if (id >= ncell) return;

    const int ix = id % D1;
    const int t  = id / D1;
    const int iy = t % D1;
    const int iz = t / D1;

    const unsigned hy0 = (unsigned)iy * PRIME_Y;
    const unsigned hy1 = hy0 + PRIME_Y;
    const unsigned hz  = (unsigned)iz * PRIME_Z;
    const unsigned ux  = (unsigned)ix;

    const float2* __restrict__ tab =
        reinterpret_cast<const float2*>(tables) + (unsigned)lvl * NGP_T;

    const float2 a00 = __ldg(tab + ((ux        ^ hy0 ^ hz) & NGP_MASK));
    const float2 a10 = __ldg(tab + (((ux + 1u) ^ hy0 ^ hz) & NGP_MASK));
    const float2 a01 = __ldg(tab + ((ux        ^ hy1 ^ hz) & NGP_MASK));
    const float2 a11 = __ldg(tab + (((ux + 1u) ^ hy1 ^ hz) & NGP_MASK));

    const __half2 h00 = __floats2half2_rn(a00.x * QSCALE, a00.y * QSCALE);
    const __half2 h10 = __floats2half2_rn(a10.x * QSCALE, a10.y * QSCALE);
    const __half2 h01 = __floats2half2_rn(a01.x * QSCALE, a01.y * QSCALE);
    const __half2 h11 = __floats2half2_rn(a11.x * QSCALE, a11.y * QSCALE);

    uint4 q;
    q.x = *reinterpret_cast<const unsigned*>(&h00);
    q.y = *reinterpret_cast<const unsigned*>(&h10);
    q.z = *reinterpret_cast<const unsigned*>(&h01);
    q.w = *reinterpret_cast<const unsigned*>(&h11);
    g_q[p.qoff[lvl - N_SMEM] + id] = q;
}

// -------- precompute C: fp16x2 hash tables for levels 7..15 -----------------
__global__ __launch_bounds__(256)
void ngp_hconv_kernel(const float* __restrict__ tables)
{
    const int t = blockIdx.x * blockDim.x + threadIdx.x;
    if (t >= NHASH * (int)(NGP_T / 4)) return;
    const float4* __restrict__ src =
        reinterpret_cast<const float4*>(tables)
        + (size_t)HBASE * (NGP_T / 2) + (size_t)t * 2;
    const float4 a = __ldg(src);
    const float4 b = __ldg(src + 1);
    const __half2 e0 = __floats2half2_rn(a.x * QSCALE, a.y * QSCALE);
    const __half2 e1 = __floats2half2_rn(a.z * QSCALE, a.w * QSCALE);
    const __half2 e2 = __floats2half2_rn(b.x * QSCALE, b.y * QSCALE);
    const __half2 e3 = __floats2half2_rn(b.z * QSCALE, b.w * QSCALE);
    uint4 q;
    q.x = *reinterpret_cast<const unsigned*>(&e0);
    q.y = *reinterpret_cast<const unsigned*>(&e1);
    q.z = *reinterpret_cast<const unsigned*>(&e2);
    q.w = *reinterpret_cast<const unsigned*>(&e3);
    g_ht[t] = q;
}

// ---------------- main kernel (persistent, smem vertex grids) ---------------
__global__ __launch_bounds__(1024, 1)
void InstantNGP_kernel(const float* __restrict__ xyz,
                       float* __restrict__ out,
                       NgpParams p, int npts)
{
    extern __shared__ unsigned sv[];   // NV_TOTAL entries

    // stage vertex grids once per block
    for (int i = threadIdx.x; i < NV_TOTAL; i += blockDim.x)
        sv[i] = g_vg[i];
    __syncthreads();

    const int t    = threadIdx.x;
    const int lvl  = t & 15;
    const int pslot = t >> 4;                 // 0..63
    const int nbatch = (npts + 63) >> 6;

    for (int b = blockIdx.x; b < nbatch; b += gridDim.x) {
        const int pt = (b << 6) + pslot;
        if (pt >= npts) continue;

        const float x = __ldg(xyz + pt * 3 + 0);
        const float y = __ldg(xyz + pt * 3 + 1);
        const float z = __ldg(xyz + pt * 3 + 2);

        const float cell = p.cell[lvl];
        const float ux = __fdiv_rn(x, cell);
        const float uy = __fdiv_rn(y, cell);
        const float uz = __fdiv_rn(z, cell);

        const float fx = floorf(ux), fy = floorf(uy), fz = floorf(uz);
        const float dx = ux - fx,    dy = uy - fy,    dz = uz - fz;

        const unsigned ix = (unsigned)(int)fx;
        const unsigned iy = (unsigned)(int)fy;
        const unsigned iz = (unsigned)(int)fz;

        const float wx0 = 1.0f - dx, wx1 = dx;
        const float wy0 = 1.0f - dy, wy1 = dy;
        const float wz0 = 1.0f - dz, wz1 = dz;

        float c0, c1;

        if (lvl < N_SMEM) {
            // ---- smem vertex grid: 8 x LDS.32 ----
            const int D  = p.vD[lvl];
            const int bse = p.voff[lvl] + ((int)iz * D + (int)iy) * D + (int)ix;
            const int DD = D * D;
            const float2 e0 = h2f(sv[bse]);
            const float2 e4 = h2f(sv[bse + 1]);
            const float2 e2 = h2f(sv[bse + D]);
            const float2 e6 = h2f(sv[bse + D + 1]);
            const float2 e1 = h2f(sv[bse + DD]);
            const float2 e5 = h2f(sv[bse + DD + 1]);
            const float2 e3 = h2f(sv[bse + DD + D]);
            const float2 e7 = h2f(sv[bse + DD + D + 1]);

            const float w0 = wx0 * wy0 * wz0;
            const float w1 = wx0 * wy0 * wz1;
            const float w2 = wx0 * wy1 * wz0;
            const float w3 = wx0 * wy1 * wz1;
            const float w4 = wx1 * wy0 * wz0;
            const float w5 = wx1 * wy0 * wz1;
            const float w6 = wx1 * wy1 * wz0;
            const float w7 = wx1 * wy1 * wz1;

            c0 = w0 * e0.x;  c1 = w0 * e0.y;
            c0 = fmaf(w1, e1.x, c0);  c1 = fmaf(w1, e1.y, c1);
            c0 = fmaf(w2, e2.x, c0);  c1 = fmaf(w2, e2.y, c1);
            c0 = fmaf(w3, e3.x, c0);  c1 = fmaf(w3, e3.y, c1);
            c0 = fmaf(w4, e4.x, c0);  c1 = fmaf(w4, e4.y, c1);
            c0 = fmaf(w5, e5.x, c0);  c1 = fmaf(w5, e5.y, c1);
            c0 = fmaf(w6, e6.x, c0);  c1 = fmaf(w6, e6.y, c1);
            c0 = fmaf(w7, e7.x, c0);  c1 = fmaf(w7, e7.y, c1);
        } else if (lvl < HBASE) {
            // ---- cell-packed global: 2 x LDG.128 ----
            const int D1 = p.res[lvl] + 1;
            const int zs = D1 * D1;
            const int base = p.qoff[lvl - N_SMEM]
                           + ((int)iz * D1 + (int)iy) * D1 + (int)ix;
            const uint4 qa = __ldg(g_q + base);
            const uint4 qb = __ldg(g_q + base + zs);

            const float2 a00 = h2f(qa.x), a10 = h2f(qa.y);
            const float2 a01 = h2f(qa.z), a11 = h2f(qa.w);
            const float2 b00 = h2f(qb.x), b10 = h2f(qb.y);
            const float2 b01 = h2f(qb.z), b11 = h2f(qb.w);

            const float w00 = wx0 * wy0, w10 = wx1 * wy0;
            const float w01 = wx0 * wy1, w11 = wx1 * wy1;

            float s0 = w00 * a00.x;            float s1 = w00 * a00.y;
            s0 = fmaf(w10, a10.x, s0);         s1 = fmaf(w10, a10.y, s1);
            s0 = fmaf(w01, a01.x, s0);         s1 = fmaf(w01, a01.y, s1);
            s0 = fmaf(w11, a11.x, s0);         s1 = fmaf(w11, a11.y, s1);
            float t0 = w00 * b00.x;            float t1 = w00 * b00.y;
            t0 = fmaf(w10, b10.x, t0);         t1 = fmaf(w10, b10.y, t1);
            t0 = fmaf(w01, b01.x, t0);         t1 = fmaf(w01, b01.y, t1);
            t0 = fmaf(w11, b11.x, t0);         t1 = fmaf(w11, b11.y, t1);

            c0 = wz0 * s0 + wz1 * t0;
            c1 = wz0 * s1 + wz1 * t1;
        } else {
            // ---- hashed: 4 quad loads (+4B extras for ix%4==3) ----
            const int hl = lvl - HBASE;
            const unsigned m0 = (iy * PRIME_Y)           ^ (iz * PRIME_Z);
            const unsigned m1 = (iy * PRIME_Y)           ^ (iz * PRIME_Z + PRIME_Z);
            const unsigned m2 = (iy * PRIME_Y + PRIME_Y) ^ (iz * PRIME_Z);
            const unsigned m3 = (iy * PRIME_Y + PRIME_Y) ^ (iz * PRIME_Z + PRIME_Z);
            const unsigned h0 = (ix ^ m0) & NGP_MASK;
            const unsigned h1 = (ix ^ m1) & NGP_MASK;
            const unsigned h2 = (ix ^ m2) & NGP_MASK;
            const unsigned h3 = (ix ^ m3) & NGP_MASK;

            const uint4* __restrict__ ht = g_ht + hl * (NGP_T / 4);
            const uint4 q0 = __ldg(ht + (h0 >> 2));
            const uint4 q1 = __ldg(ht + (h1 >> 2));
            const uint4 q2 = __ldg(ht + (h2 >> 2));
            const uint4 q3 = __ldg(ht + (h3 >> 2));

            const unsigned jx = ix + 1u;
            const bool extra = (ix & 3u) == 3u;
            float2 e4, e5, e6, e7;
            if (extra) {
                const unsigned* __restrict__ ht32 =
                    reinterpret_cast<const unsigned*>(g_ht) + hl * NGP_T;
                const unsigned v4 = __ldg(ht32 + ((jx ^ m0) & NGP_MASK));
                const unsigned v5 = __ldg(ht32 + ((jx ^ m1) & NGP_MASK));
                const unsigned v6 = __ldg(ht32 + ((jx ^ m2) & NGP_MASK));
                const unsigned v7 = __ldg(ht32 + ((jx ^ m3) & NGP_MASK));
                e4 = h2f(v4); e5 = h2f(v5); e6 = h2f(v6); e7 = h2f(v7);
            } else {
                e4 = hsel(q0, (jx ^ m0) & 3u);
                e5 = hsel(q1, (jx ^ m1) & 3u);
                e6 = hsel(q2, (jx ^ m2) & 3u);
                e7 = hsel(q3, (jx ^ m3) & 3u);
            }
            const float2 e0 = hsel(q0, h0 & 3u);
            const float2 e1 = hsel(q1, h1 & 3u);
            const float2 e2 = hsel(q2, h2 & 3u);
            const float2 e3 = hsel(q3, h3 & 3u);

            const float w0 = wx0 * wy0 * wz0;
            const float w1 = wx0 * wy0 * wz1;
            const float w2 = wx0 * wy1 * wz0;
            const float w3 = wx0 * wy1 * wz1;
            const float w4 = wx1 * wy0 * wz0;
            const float w5 = wx1 * wy0 * wz1;
            const float w6 = wx1 * wy1 * wz0;
            const float w7 = wx1 * wy1 * wz1;

            c0 = w0 * e0.x;  c1 = w0 * e0.y;
            c0 = fmaf(w1, e1.x, c0);  c1 = fmaf(w1, e1.y, c1);
            c0 = fmaf(w2, e2.x, c0);  c1 = fmaf(w2, e2.y, c1);
            c0 = fmaf(w3, e3.x, c0);  c1 = fmaf(w3, e3.y, c1);
            c0 = fmaf(w4, e4.x, c0);  c1 = fmaf(w4, e4.y, c1);
            c0 = fmaf(w5, e5.x, c0);  c1 = fmaf(w5, e5.y, c1);
            c0 = fmaf(w6, e6.x, c0);  c1 = fmaf(w6, e6.y, c1);
            c0 = fmaf(w7, e7.x, c0);  c1 = fmaf(w7, e7.y, c1);
        }

        reinterpret_cast<float2*>(out)[pt * NGP_L + lvl] =
            make_float2(c0 * QSCALE_I, c1 * QSCALE_I);
    }
}

extern "C" void kernel_launch(void* const* d_in, const int* in_sizes, int n_in,
                              void* d_out, int out_size)
{
    const float* xyz    = (const float*)d_in[0];
    const float* tables = (const float*)d_in[1];
    float* out          = (float*)d_out;
    const int npts = in_sizes[0] / 3;

    // Reference resolution chain, replicated exactly in libm double.
    NgpParams p;
    const double B = std::exp((std::log(2048.0) - std::log(16.0)) / 15.0);
    for (int i = 0; i < NGP_L; i++) {
        double res_d = std::floor(16.0 * std::pow(B, (double)i));
        float resf   = (float)res_d;
        p.cell[i] = 1.0f / resf;
        p.res[i]  = (int)res_d;
    }
    int voff = 0;
    for (int i = 0; i < N_SMEM; i++) {
        p.voff[i] = voff;
        p.vD[i]   = p.res[i] + 2;
        voff += p.vD[i] * p.vD[i] * p.vD[i];
    }
    int qoff = 0, max_ncell = 0;
    for (int i = 0; i < N_CELL; i++) {
        const int r = p.res[N_SMEM + i];
        p.qoff[i] = qoff;
        const int n = (r + 1) * (r + 1) * (r + 2);
        qoff += n;
        if (n > max_ncell) max_ncell = n;
    }

    // 1) vertex grids for smem levels
    ngp_vpack_kernel<<<(NV_TOTAL + 255) / 256, 256>>>(tables, p);
    // 2) cell-packed tables for levels 3-6
    {
        dim3 grid((max_ncell + 255) / 256, N_CELL);
        ngp_qpack_kernel<<<grid, 256>>>(tables, p);
    }
    // 3) fp16 hash tables for levels 7-15
    {
        const int nth = NHASH * ((int)NGP_T / 4);
        ngp_hconv_kernel<<<(nth + 255) / 256, 256>>>(tables);
    }
    // 4) main encode (persistent blocks, dynamic smem = vertex grids)
    {
        const int smem_bytes = NV_TOTAL * 4;
        cudaFuncSetAttribute(InstantNGP_kernel,
                             cudaFuncAttributeMaxDynamicSharedMemorySize,
                             smem_bytes);
        InstantNGP_kernel<<<152, 1024, smem_bytes>>>(xyz, out, p, npts);
    }
}

// round 7
// speedup vs baseline: 1.2844x; 1.2844x over previous
#include <cuda_runtime.h>
#include <cuda_fp16.h>
#include <cmath>
#include <cstdint>

// InstantNGP hash-grid encoder, round 7.
//  * levels 0-6: cell-packed fp16 tables in global memory.
//    Query = 2 x LDG.128 (z0,z1 cells) for all 8 corners.
//  * levels 7-15: fp16x2 (4B) hash tables; LDG.128 covers a 4-entry window.
//    x-prime==1 => windows cover both x-corners for ix%4 != 3 (75%): 4 loads;
//    ix%4==3 lanes add 4 x 4B gathers. avg 5 loads/level.
//  * single fused precompute kernel (hconv + qpack, independent items).
//  * xyz fetched once per warp by lanes 0-5, distributed via shfl.

#define NGP_L 16
#define NGP_T (1u << 19)
#define NGP_MASK ((1u << 19) - 1u)
#define PRIME_Y 2654435761u
#define PRIME_Z 805459861u

#define N_CELL 7                    // levels 0-6 cell-packed
#define NHASH  (NGP_L - N_CELL)     // 9 hashed levels (7-15)

#define QSCALE   65536.0f
#define QSCALE_I (1.0f / 65536.0f)

// cell-packed l0-6: sum (r+1)^2*(r+2) = 2,294,340 entries, 16B each
#define QCAP 2300000
__device__ uint4 g_q[QCAP];

// hashed fp16 tables l7-15: 9 * 2^19 * 4B viewed as quads
#define HCONV_ITEMS (NHASH * (int)(NGP_T / 4))
__device__ uint4 g_ht[NHASH * (NGP_T / 4)];

struct NgpParams {
    float cell[NGP_L];
    int   res[NGP_L];
    int   qoff[N_CELL];      // offset of level's cell table in g_q
    int   ccum[N_CELL + 1];  // cumulative cell counts (for work-item decode)
};

__device__ __forceinline__ float2 hsel(const uint4& q, unsigned i)
{
    const unsigned v = (i & 2u) ? ((i & 1u) ? q.w : q.z)
                                : ((i & 1u) ? q.y : q.x);
    return __half22float2(*reinterpret_cast<const __half2*>(&v));
}
__device__ __forceinline__ float2 h2f(unsigned v)
{
    return __half22float2(*reinterpret_cast<const __half2*>(&v));
}

// -------- fused precompute: hconv (l7-15) + qpack (l0-6) --------------------
__global__ __launch_bounds__(256)
void ngp_prep_kernel(const float* __restrict__ tables, NgpParams p, int ntot)
{
    const int id = blockIdx.x * blockDim.x + threadIdx.x;
    if (id >= ntot) return;

    if (id < HCONV_ITEMS) {
        // ---- convert 4 hash entries of levels 7-15 to scaled fp16 ----
        const float4* __restrict__ src =
            reinterpret_cast<const float4*>(tables)
            + (size_t)N_CELL * (NGP_T / 2) + (size_t)id * 2;
        const float4 a = __ldg(src);
        const float4 b = __ldg(src + 1);
        const __half2 e0 = __floats2half2_rn(a.x * QSCALE, a.y * QSCALE);
        const __half2 e1 = __floats2half2_rn(a.z * QSCALE, a.w * QSCALE);
        const __half2 e2 = __floats2half2_rn(b.x * QSCALE, b.y * QSCALE);
        const __half2 e3 = __floats2half2_rn(b.z * QSCALE, b.w * QSCALE);
        uint4 q;
        q.x = *reinterpret_cast<const unsigned*>(&e0);
        q.y = *reinterpret_cast<const unsigned*>(&e1);
        q.z = *reinterpret_cast<const unsigned*>(&e2);
        q.w = *reinterpret_cast<const unsigned*>(&e3);
        g_ht[id] = q;
        return;
    }

    // ---- cell-pack one cell of levels 0-6 ----
    int rel = id - HCONV_ITEMS;
    int lvl = 0;
    #pragma unroll
    for (int l = 0; l < N_CELL; l++)
        if (rel >= p.ccum[l] && rel < p.ccum[l + 1]) lvl = l;
    rel -= p.ccum[lvl];

    const int res = p.res[lvl];
    const int D1  = res + 1;
    const int ix  = rel % D1;
    const int t   = rel / D1;
    const int iy  = t % D1;
    const int iz  = t / D1;

    const unsigned hy0 = (unsigned)iy * PRIME_Y;
    const unsigned hy1 = hy0 + PRIME_Y;
    const unsigned hz  = (unsigned)iz * PRIME_Z;
    const unsigned ux  = (unsigned)ix;

    const float2* __restrict__ tab =
        reinterpret_cast<const float2*>(tables) + (unsigned)lvl * NGP_T;

    // consecutive rel -> consecutive ix: heavy sector sharing in these gathers
    const float2 a00 = __ldg(tab + ((ux        ^ hy0 ^ hz) & NGP_MASK));
    const float2 a10 = __ldg(tab + (((ux + 1u) ^ hy0 ^ hz) & NGP_MASK));
    const float2 a01 = __ldg(tab + ((ux        ^ hy1 ^ hz) & NGP_MASK));
    const float2 a11 = __ldg(tab + (((ux + 1u) ^ hy1 ^ hz) & NGP_MASK));

    const __half2 h00 = __floats2half2_rn(a00.x * QSCALE, a00.y * QSCALE);
    const __half2 h10 = __floats2half2_rn(a10.x * QSCALE, a10.y * QSCALE);
    const __half2 h01 = __floats2half2_rn(a01.x * QSCALE, a01.y * QSCALE);
    const __half2 h11 = __floats2half2_rn(a11.x * QSCALE, a11.y * QSCALE);

    uint4 q;
    q.x = *reinterpret_cast<const unsigned*>(&h00);
    q.y = *reinterpret_cast<const unsigned*>(&h10);
    q.z = *reinterpret_cast<const unsigned*>(&h01);
    q.w = *reinterpret_cast<const unsigned*>(&h11);
    g_q[p.qoff[lvl] + rel] = q;
}

// ---------------- main kernel ----------------------------------------------
__global__ __launch_bounds__(256)
void InstantNGP_kernel(const float* __restrict__ xyz,
                       float* __restrict__ out,
                       NgpParams p, int npts)
{
    const int gid  = blockIdx.x * blockDim.x + threadIdx.x;
    const int pt   = gid >> 4;
    const int lvl  = gid & 15;
    if (pt >= npts) return;

    // warp covers pts {A, A+1}: lanes 0-5 load 6 contiguous floats, shfl out.
    const int lane = threadIdx.x & 31;
    const int ptA  = (blockIdx.x * blockDim.x + (threadIdx.x & ~31)) >> 4;
    float v = 0.0f;
    if (lane < 6) v = __ldg(xyz + ptA * 3 + lane);
    const int s = (lane >> 4) * 3;
    const float x = __shfl_sync(0xffffffffu, v, s + 0);
    const float y = __shfl_sync(0xffffffffu, v, s + 1);
    const float z = __shfl_sync(0xffffffffu, v, s + 2);

    const float cell = p.cell[lvl];
    const float ux = __fdiv_rn(x, cell);
    const float uy = __fdiv_rn(y, cell);
    const float uz = __fdiv_rn(z, cell);

    const float fx = floorf(ux), fy = floorf(uy), fz = floorf(uz);
    const float dx = ux - fx,    dy = uy - fy,    dz = uz - fz;

    const unsigned ix = (unsigned)(int)fx;
    const unsigned iy = (unsigned)(int)fy;
    const unsigned iz = (unsigned)(int)fz;

    const float wx0 = 1.0f - dx, wx1 = dx;
    const float wy0 = 1.0f - dy, wy1 = dy;
    const float wz0 = 1.0f - dz, wz1 = dz;

    float c0, c1;

    if (lvl < N_CELL) {
        // ---- cell-packed: 2 x LDG.128 fetch all 8 corners ----
        const int D1 = p.res[lvl] + 1;
        const int zs = D1 * D1;
        const int base = p.qoff[lvl] + ((int)iz * D1 + (int)iy) * D1 + (int)ix;
        const uint4 qa = __ldg(g_q + base);        // z = iz
        const uint4 qb = __ldg(g_q + base + zs);   // z = iz+1

        const float2 a00 = h2f(qa.x), a10 = h2f(qa.y);
        const float2 a01 = h2f(qa.z), a11 = h2f(qa.w);
        const float2 b00 = h2f(qb.x), b10 = h2f(qb.y);
        const float2 b01 = h2f(qb.z), b11 = h2f(qb.w);

        const float w00 = wx0 * wy0, w10 = wx1 * wy0;
        const float w01 = wx0 * wy1, w11 = wx1 * wy1;

        float s0 = w00 * a00.x;            float s1 = w00 * a00.y;
        s0 = fmaf(w10, a10.x, s0);         s1 = fmaf(w10, a10.y, s1);
        s0 = fmaf(w01, a01.x, s0);         s1 = fmaf(w01, a01.y, s1);
        s0 = fmaf(w11, a11.x, s0);         s1 = fmaf(w11, a11.y, s1);
        float t0 = w00 * b00.x;            float t1 = w00 * b00.y;
        t0 = fmaf(w10, b10.x, t0);         t1 = fmaf(w10, b10.y, t1);
        t0 = fmaf(w01, b01.x, t0);         t1 = fmaf(w01, b01.y, t1);
        t0 = fmaf(w11, b11.x, t0);         t1 = fmaf(w11, b11.y, t1);

        c0 = wz0 * s0 + wz1 * t0;
        c1 = wz0 * s1 + wz1 * t1;
    } else {
        // ---- hashed: 4 quad loads (+4B extras for ix%4==3 lanes) ----
        const int hl = lvl - N_CELL;
        const unsigned m0 = (iy * PRIME_Y)           ^ (iz * PRIME_Z);
        const unsigned m1 = (iy * PRIME_Y)           ^ (iz * PRIME_Z + PRIME_Z);
        const unsigned m2 = (iy * PRIME_Y + PRIME_Y) ^ (iz * PRIME_Z);
        const unsigned m3 = (iy * PRIME_Y + PRIME_Y) ^ (iz * PRIME_Z + PRIME_Z);
        const unsigned h0 = (ix ^ m0) & NGP_MASK;
        const unsigned h1 = (ix ^ m1) & NGP_MASK;
        const unsigned h2 = (ix ^ m2) & NGP_MASK;
        const unsigned h3 = (ix ^ m3) & NGP_MASK;

        const uint4* __restrict__ ht = g_ht + hl * (NGP_T / 4);
        const uint4 q0 = __ldg(ht + (h0 >> 2));
        const uint4 q1 = __ldg(ht + (h1 >> 2));
        const uint4 q2 = __ldg(ht + (h2 >> 2));
        const uint4 q3 = __ldg(ht + (h3 >> 2));

        const unsigned jx = ix + 1u;
        const bool extra = (ix & 3u) == 3u;
        float2 e4, e5, e6, e7;
        if (extra) {
            const unsigned* __restrict__ ht32 =
                reinterpret_cast<const unsigned*>(g_ht) + hl * NGP_T;
            const unsigned v4 = __ldg(ht32 + ((jx ^ m0) & NGP_MASK));
            const unsigned v5 = __ldg(ht32 + ((jx ^ m1) & NGP_MASK));
            const unsigned v6 = __ldg(ht32 + ((jx ^ m2) & NGP_MASK));
            const unsigned v7 = __ldg(ht32 + ((jx ^ m3) & NGP_MASK));
            e4 = h2f(v4); e5 = h2f(v5); e6 = h2f(v6); e7 = h2f(v7);
        } else {
            e4 = hsel(q0, (jx ^ m0) & 3u);
            e5 = hsel(q1, (jx ^ m1) & 3u);
            e6 = hsel(q2, (jx ^ m2) & 3u);
            e7 = hsel(q3, (jx ^ m3) & 3u);
        }
        const float2 e0 = hsel(q0, h0 & 3u);
        const float2 e1 = hsel(q1, h1 & 3u);
        const float2 e2 = hsel(q2, h2 & 3u);
        const float2 e3 = hsel(q3, h3 & 3u);

        const float w0 = wx0 * wy0 * wz0;
        const float w1 = wx0 * wy0 * wz1;
        const float w2 = wx0 * wy1 * wz0;
        const float w3 = wx0 * wy1 * wz1;
        const float w4 = wx1 * wy0 * wz0;
        const float w5 = wx1 * wy0 * wz1;
        const float w6 = wx1 * wy1 * wz0;
        const float w7 = wx1 * wy1 * wz1;

        c0 = w0 * e0.x;  c1 = w0 * e0.y;
        c0 = fmaf(w1, e1.x, c0);  c1 = fmaf(w1, e1.y, c1);
        c0 = fmaf(w2, e2.x, c0);  c1 = fmaf(w2, e2.y, c1);
        c0 = fmaf(w3, e3.x, c0);  c1 = fmaf(w3, e3.y, c1);
        c0 = fmaf(w4, e4.x, c0);  c1 = fmaf(w4, e4.y, c1);
        c0 = fmaf(w5, e5.x, c0);  c1 = fmaf(w5, e5.y, c1);
        c0 = fmaf(w6, e6.x, c0);  c1 = fmaf(w6, e6.y, c1);
        c0 = fmaf(w7, e7.x, c0);  c1 = fmaf(w7, e7.y, c1);
    }

    reinterpret_cast<float2*>(out)[pt * NGP_L + lvl] =
        make_float2(c0 * QSCALE_I, c1 * QSCALE_I);
}

extern "C" void kernel_launch(void* const* d_in, const int* in_sizes, int n_in,
                              void* d_out, int out_size)
{
    const float* xyz    = (const float*)d_in[0];
    const float* tables = (const float*)d_in[1];
    float* out          = (float*)d_out;
    const int npts = in_sizes[0] / 3;

    // Reference resolution chain, replicated exactly in libm double.
    NgpParams p;
    const double B = std::exp((std::log(2048.0) - std::log(16.0)) / 15.0);
    for (int i = 0; i < NGP_L; i++) {
        double res_d = std::floor(16.0 * std::pow(B, (double)i));
        float resf   = (float)res_d;
        p.cell[i] = 1.0f / resf;
        p.res[i]  = (int)res_d;
    }
    int qoff = 0;
    p.ccum[0] = 0;
    for (int i = 0; i < N_CELL; i++) {
        p.qoff[i] = qoff;
        const int r = p.res[i];
        const int n = (r + 1) * (r + 1) * (r + 2);
        qoff += n;
        p.ccum[i + 1] = p.ccum[i] + n;
    }
    // qoff = 2,294,340 <= QCAP for the reference chain.

    // 1) fused precompute (hash fp16 conversion + cell packing)
    {
        const int ntot = HCONV_ITEMS + p.ccum[N_CELL];
        ngp_prep_kernel<<<(ntot + 255) / 256, 256>>>(tables, p, ntot);
    }
    // 2) main encode
    {
        const int total = npts * NGP_L;
        InstantNGP_kernel<<<(total + 255) / 256, 256>>>(xyz, out, p, npts);
    }
}

// round 8
// speedup vs baseline: 2.0418x; 1.5897x over previous
#include <cuda_runtime.h>
#include <cuda_fp16.h>
#include <cmath>
#include <cstdint>

// InstantNGP hash-grid encoder, round 8 = round 5 structure + fused prep
// + cell-packing extended by exactly one level (level 5).
//  * levels 0-5: cell-packed fp16 tables (2 x LDG.128 per query).
//  * levels 6-15: fp16x2 hash tables, 4-entry LDG.128 windows; ix%4==3
//    lanes add 4 x 4B gathers (avg 5 lines/level).

#define NGP_L 16
#define NGP_T (1u << 19)
#define NGP_MASK ((1u << 19) - 1u)
#define PRIME_Y 2654435761u
#define PRIME_Z 805459861u

#define N_CELL 6                    // levels 0-5 cell-packed
#define NHASH  (NGP_L - N_CELL)     // 10 hashed levels (6-15)

#define QSCALE   65536.0f
#define QSCALE_I (1.0f / 65536.0f)

// cell-packed l0-5: sum (r+1)^2*(r+2) = 876,868 entries, 16B each
#define QCAP 880000
__device__ uint4 g_q[QCAP];

// hashed fp16 tables l6-15: 10 * 2^19 * 4B viewed as quads
#define HCONV_ITEMS (NHASH * (int)(NGP_T / 4))
__device__ uint4 g_ht[NHASH * (NGP_T / 4)];

struct NgpParams {
    float cell[NGP_L];
    int   res[NGP_L];
    int   qoff[N_CELL];
    int   ccum[N_CELL + 1];
};

__device__ __forceinline__ float2 hsel(const uint4& q, unsigned i)
{
    const unsigned v = (i & 2u) ? ((i & 1u) ? q.w : q.z)
                                : ((i & 1u) ? q.y : q.x);
    return __half22float2(*reinterpret_cast<const __half2*>(&v));
}
__device__ __forceinline__ float2 h2f(unsigned v)
{
    return __half22float2(*reinterpret_cast<const __half2*>(&v));
}

// -------- fused precompute: hconv (l6-15) + qpack (l0-5) --------------------
__global__ __launch_bounds__(256)
void ngp_prep_kernel(const float* __restrict__ tables, NgpParams p, int ntot)
{
    const int id = blockIdx.x * blockDim.x + threadIdx.x;
    if (id >= ntot) return;

    if (id < HCONV_ITEMS) {
        // convert 4 hash entries of levels 6-15 to scaled fp16 (coalesced)
        const float4* __restrict__ src =
            reinterpret_cast<const float4*>(tables)
            + (size_t)N_CELL * (NGP_T / 2) + (size_t)id * 2;
        const float4 a = __ldg(src);
        const float4 b = __ldg(src + 1);
        const __half2 e0 = __floats2half2_rn(a.x * QSCALE, a.y * QSCALE);
        const __half2 e1 = __floats2half2_rn(a.z * QSCALE, a.w * QSCALE);
        const __half2 e2 = __floats2half2_rn(b.x * QSCALE, b.y * QSCALE);
        const __half2 e3 = __floats2half2_rn(b.z * QSCALE, b.w * QSCALE);
        uint4 q;
        q.x = *reinterpret_cast<const unsigned*>(&e0);
        q.y = *reinterpret_cast<const unsigned*>(&e1);
        q.z = *reinterpret_cast<const unsigned*>(&e2);
        q.w = *reinterpret_cast<const unsigned*>(&e3);
        g_ht[id] = q;
        return;
    }

    // cell-pack one cell of levels 0-5
    int rel = id - HCONV_ITEMS;
    int lvl = 0;
    #pragma unroll
    for (int l = 0; l < N_CELL; l++)
        if (rel >= p.ccum[l] && rel < p.ccum[l + 1]) lvl = l;
    rel -= p.ccum[lvl];

    const int res = p.res[lvl];
    const int D1  = res + 1;
    const int ix  = rel % D1;
    const int t   = rel / D1;
    const int iy  = t % D1;
    const int iz  = t / D1;

    const unsigned hy0 = (unsigned)iy * PRIME_Y;
    const unsigned hy1 = hy0 + PRIME_Y;
    const unsigned hz  = (unsigned)iz * PRIME_Z;
    const unsigned ux  = (unsigned)ix;

    const float2* __restrict__ tab =
        reinterpret_cast<const float2*>(tables) + (unsigned)lvl * NGP_T;

    const float2 a00 = __ldg(tab + ((ux        ^ hy0 ^ hz) & NGP_MASK));
    const float2 a10 = __ldg(tab + (((ux + 1u) ^ hy0 ^ hz) & NGP_MASK));
    const float2 a01 = __ldg(tab + ((ux        ^ hy1 ^ hz) & NGP_MASK));
    const float2 a11 = __ldg(tab + (((ux + 1u) ^ hy1 ^ hz) & NGP_MASK));

    const __half2 h00 = __floats2half2_rn(a00.x * QSCALE, a00.y * QSCALE);
    const __half2 h10 = __floats2half2_rn(a10.x * QSCALE, a10.y * QSCALE);
    const __half2 h01 = __floats2half2_rn(a01.x * QSCALE, a01.y * QSCALE);
    const __half2 h11 = __floats2half2_rn(a11.x * QSCALE, a11.y * QSCALE);

    uint4 q;
    q.x = *reinterpret_cast<const unsigned*>(&h00);
    q.y = *reinterpret_cast<const unsigned*>(&h10);
    q.z = *reinterpret_cast<const unsigned*>(&h01);
    q.w = *reinterpret_cast<const unsigned*>(&h11);
    g_q[p.qoff[lvl] + rel] = q;
}

// ---------------- main kernel (round-5 structure) ---------------------------
__global__ __launch_bounds__(256)
void InstantNGP_kernel(const float* __restrict__ xyz,
                       float* __restrict__ out,
                       NgpParams p, int npts)
{
    const int gid = blockIdx.x * blockDim.x + threadIdx.x;
    const int pt  = gid >> 4;
    const int lvl = gid & 15;
    if (pt >= npts) return;

    const float x = __ldg(xyz + pt * 3 + 0);
    const float y = __ldg(xyz + pt * 3 + 1);
    const float z = __ldg(xyz + pt * 3 + 2);

    const float cell = p.cell[lvl];
    const float ux = __fdiv_rn(x, cell);
    const float uy = __fdiv_rn(y, cell);
    const float uz = __fdiv_rn(z, cell);

    const float fx = floorf(ux), fy = floorf(uy), fz = floorf(uz);
    const float dx = ux - fx,    dy = uy - fy,    dz = uz - fz;

    const unsigned ix = (unsigned)(int)fx;
    const unsigned iy = (unsigned)(int)fy;
    const unsigned iz = (unsigned)(int)fz;

    const float wx0 = 1.0f - dx, wx1 = dx;
    const float wy0 = 1.0f - dy, wy1 = dy;
    const float wz0 = 1.0f - dz, wz1 = dz;

    float c0, c1;

    if (lvl < N_CELL) {
        // ---- cell-packed: 2 x LDG.128 fetch all 8 corners ----
        const int D1 = p.res[lvl] + 1;
        const int zs = D1 * D1;
        const int base = p.qoff[lvl] + ((int)iz * D1 + (int)iy) * D1 + (int)ix;
        const uint4 qa = __ldg(g_q + base);        // z = iz
        const uint4 qb = __ldg(g_q + base + zs);   // z = iz+1

        const float2 a00 = h2f(qa.x), a10 = h2f(qa.y);
        const float2 a01 = h2f(qa.z), a11 = h2f(qa.w);
        const float2 b00 = h2f(qb.x), b10 = h2f(qb.y);
        const float2 b01 = h2f(qb.z), b11 = h2f(qb.w);

        const float w00 = wx0 * wy0, w10 = wx1 * wy0;
        const float w01 = wx0 * wy1, w11 = wx1 * wy1;

        float s0 = w00 * a00.x;            float s1 = w00 * a00.y;
        s0 = fmaf(w10, a10.x, s0);         s1 = fmaf(w10, a10.y, s1);
        s0 = fmaf(w01, a01.x, s0);         s1 = fmaf(w01, a01.y, s1);
        s0 = fmaf(w11, a11.x, s0);         s1 = fmaf(w11, a11.y, s1);
        float t0 = w00 * b00.x;            float t1 = w00 * b00.y;
        t0 = fmaf(w10, b10.x, t0);         t1 = fmaf(w10, b10.y, t1);
        t0 = fmaf(w01, b01.x, t0);         t1 = fmaf(w01, b01.y, t1);
        t0 = fmaf(w11, b11.x, t0);         t1 = fmaf(w11, b11.y, t1);

        c0 = wz0 * s0 + wz1 * t0;
        c1 = wz0 * s1 + wz1 * t1;
    } else {
        // ---- hashed: 4 quad loads (+4B extras for ix%4==3 lanes) ----
        const int hl = lvl - N_CELL;
        const unsigned m0 = (iy * PRIME_Y)           ^ (iz * PRIME_Z);
        const unsigned m1 = (iy * PRIME_Y)           ^ (iz * PRIME_Z + PRIME_Z);
        const unsigned m2 = (iy * PRIME_Y + PRIME_Y) ^ (iz * PRIME_Z);
        const unsigned m3 = (iy * PRIME_Y + PRIME_Y) ^ (iz * PRIME_Z + PRIME_Z);
        const unsigned h0 = (ix ^ m0) & NGP_MASK;
        const unsigned h1 = (ix ^ m1) & NGP_MASK;
        const unsigned h2 = (ix ^ m2) & NGP_MASK;
        const unsigned h3 = (ix ^ m3) & NGP_MASK;

        const uint4* __restrict__ ht = g_ht + hl * (NGP_T / 4);
        const uint4 q0 = __ldg(ht + (h0 >> 2));
        const uint4 q1 = __ldg(ht + (h1 >> 2));
        const uint4 q2 = __ldg(ht + (h2 >> 2));
        const uint4 q3 = __ldg(ht + (h3 >> 2));

        const unsigned jx = ix + 1u;
        const bool extra = (ix & 3u) == 3u;
        float2 e4, e5, e6, e7;
        if (extra) {
            const unsigned* __restrict__ ht32 =
                reinterpret_cast<const unsigned*>(g_ht) + hl * NGP_T;
            const unsigned v4 = __ldg(ht32 + ((jx ^ m0) & NGP_MASK));
            const unsigned v5 = __ldg(ht32 + ((jx ^ m1) & NGP_MASK));
            const unsigned v6 = __ldg(ht32 + ((jx ^ m2) & NGP_MASK));
            const unsigned v7 = __ldg(ht32 + ((jx ^ m3) & NGP_MASK));
            e4 = h2f(v4); e5 = h2f(v5); e6 = h2f(v6); e7 = h2f(v7);
        } else {
            e4 = hsel(q0, (jx ^ m0) & 3u);
            e5 = hsel(q1, (jx ^ m1) & 3u);
            e6 = hsel(q2, (jx ^ m2) & 3u);
            e7 = hsel(q3, (jx ^ m3) & 3u);
        }
        const float2 e0 = hsel(q0, h0 & 3u);
        const float2 e1 = hsel(q1, h1 & 3u);
        const float2 e2 = hsel(q2, h2 & 3u);
        const float2 e3 = hsel(q3, h3 & 3u);

        const float w0 = wx0 * wy0 * wz0;
        const float w1 = wx0 * wy0 * wz1;
        const float w2 = wx0 * wy1 * wz0;
        const float w3 = wx0 * wy1 * wz1;
        const float w4 = wx1 * wy0 * wz0;
        const float w5 = wx1 * wy0 * wz1;
        const float w6 = wx1 * wy1 * wz0;
        const float w7 = wx1 * wy1 * wz1;

        c0 = w0 * e0.x;  c1 = w0 * e0.y;
        c0 = fmaf(w1, e1.x, c0);  c1 = fmaf(w1, e1.y, c1);
        c0 = fmaf(w2, e2.x, c0);  c1 = fmaf(w2, e2.y, c1);
        c0 = fmaf(w3, e3.x, c0);  c1 = fmaf(w3, e3.y, c1);
        c0 = fmaf(w4, e4.x, c0);  c1 = fmaf(w4, e4.y, c1);
        c0 = fmaf(w5, e5.x, c0);  c1 = fmaf(w5, e5.y, c1);
        c0 = fmaf(w6, e6.x, c0);  c1 = fmaf(w6, e6.y, c1);
        c0 = fmaf(w7, e7.x, c0);  c1 = fmaf(w7, e7.y, c1);
    }

    reinterpret_cast<float2*>(out)[pt * NGP_L + lvl] =
        make_float2(c0 * QSCALE_I, c1 * QSCALE_I);
}

extern "C" void kernel_launch(void* const* d_in, const int* in_sizes, int n_in,
                              void* d_out, int out_size)
{
    const float* xyz    = (const float*)d_in[0];
    const float* tables = (const float*)d_in[1];
    float* out          = (float*)d_out;
    const int npts = in_sizes[0] / 3;

    // Reference resolution chain, replicated exactly in libm double.
    NgpParams p;
    const double B = std::exp((std::log(2048.0) - std::log(16.0)) / 15.0);
    for (int i = 0; i < NGP_L; i++) {
        double res_d = std::floor(16.0 * std::pow(B, (double)i));
        float resf   = (float)res_d;
        p.cell[i] = 1.0f / resf;
        p.res[i]  = (int)res_d;
    }
    int qoff = 0;
    p.ccum[0] = 0;
    for (int i = 0; i < N_CELL; i++) {
        p.qoff[i] = qoff;
        const int r = p.res[i];
        const int n = (r + 1) * (r + 1) * (r + 2);
        qoff += n;
        p.ccum[i + 1] = p.ccum[i] + n;
    }
    // qoff = 876,868 <= QCAP for the reference chain.

    // 1) fused precompute (hash fp16 conversion + cell packing)
    {
        const int ntot = HCONV_ITEMS + p.ccum[N_CELL];
        ngp_prep_kernel<<<(ntot + 255) / 256, 256>>>(tables, p, ntot);
    }
    // 2) main encode
    {
        const int total = npts * NGP_L;
        InstantNGP_kernel<<<(total + 255) / 256, 256>>>(xyz, out, p, npts);
    }
}